// round 4
// baseline (speedup 1.0000x reference)
#include <cuda_runtime.h>
#include <math.h>

// Shape (2,3,128,128,128) fp32
#define NTOT   12582912
#define NROWS  98304
#define HROWS  49152          // NROWS/2 ; halves live in volumes 0-2 / 3-5
#define ALPHA  0.001
#define WPB    4              // warps per block
#define BLOCK  (WPB * 32)
#define GRID   (HROWS / WPB)  // 12288

// ---------------- packed f32x2 helpers ----------------
typedef unsigned long long u64f2;

__device__ __forceinline__ u64f2 pk2(float lo, float hi) {
    u64f2 r; asm("mov.b64 %0, {%1, %2};" : "=l"(r) : "f"(lo), "f"(hi)); return r;
}
__device__ __forceinline__ void un2(u64f2 v, float& lo, float& hi) {
    asm("mov.b64 {%0, %1}, %2;" : "=f"(lo), "=f"(hi) : "l"(v));
}
__device__ __forceinline__ u64f2 add2(u64f2 a, u64f2 b) {
    u64f2 r; asm("add.rn.f32x2 %0, %1, %2;" : "=l"(r) : "l"(a), "l"(b)); return r;
}
__device__ __forceinline__ u64f2 mul2(u64f2 a, u64f2 b) {
    u64f2 r; asm("mul.rn.f32x2 %0, %1, %2;" : "=l"(r) : "l"(a), "l"(b)); return r;
}
__device__ __forceinline__ u64f2 fma2_(u64f2 a, u64f2 b, u64f2 c) {
    u64f2 r; asm("fma.rn.f32x2 %0, %1, %2, %3;" : "=l"(r) : "l"(a), "l"(b), "l"(c)); return r;
}

#define ONE2   0x3F8000003F800000ull   //  1.0f | 1.0f
#define NEG12  0xBF800000BF800000ull   // -1.0f
#define NEG22  0xC0000000C0000000ull   // -2.0f
#define QTR2   0x3E8000003E800000ull   //  0.25f
#define EPS2b  0x322BCC77322BCC77ull   //  1e-8f

__device__ __forceinline__ u64f2 sub2(u64f2 a, u64f2 b) { return fma2_(b, (u64f2)NEG12, a); }

struct Win { u64f2 w[6]; };            // [0]=x-1 edge, [1..4]=vals, [5]=x+1 edge
struct P4  { u64f2 v[4]; };

__device__ __forceinline__ Win mkwin(float4 A, float4 B, int lane) {
    const unsigned FULL = 0xFFFFFFFFu;
    Win W;
    W.w[1] = pk2(A.x, B.x); W.w[2] = pk2(A.y, B.y);
    W.w[3] = pk2(A.z, B.z); W.w[4] = pk2(A.w, B.w);
    u64f2 L = __shfl_up_sync(FULL, W.w[4], 1);
    u64f2 R = __shfl_down_sync(FULL, W.w[1], 1);
    W.w[0] = (lane == 0)  ? W.w[1] : L;   // clamp x=0
    W.w[5] = (lane == 31) ? W.w[4] : R;   // clamp x=127
    return W;
}
__device__ __forceinline__ P4 mkp4(float4 A, float4 B) {
    P4 P;
    P.v[0] = pk2(A.x, B.x); P.v[1] = pk2(A.y, B.y);
    P.v[2] = pk2(A.z, B.z); P.v[3] = pk2(A.w, B.w);
    return P;
}

__device__ double       g_acc[3];
__device__ unsigned int g_ticket;

__global__ __launch_bounds__(BLOCK) void ace_main(
    const float* __restrict__ yp, const float* __restrict__ yt,
    float* __restrict__ out)
{
    const unsigned FULL = 0xFFFFFFFFu;
    const int wid  = threadIdx.x >> 5;
    const int lane = threadIdx.x & 31;
    const int rA   = blockIdx.x * WPB + wid;        // row in half A; half B = rA + HROWS

    const int y = rA & 127;
    const int z = (rA >> 7) & 127;
    const int ym_ = y > 0   ? y - 1 : 0;
    const int yq  = y < 127 ? y + 1 : 127;
    const int zm_ = z > 0   ? z - 1 : 0;
    const int zq  = z < 127 ? z + 1 : 127;

    const size_t vbA = (size_t)(rA >> 14) << 21;
    const float* UA = yp + vbA;
    const float* UB = UA + ((size_t)3 << 21);

    #define RP(U,zz,yy) (((const float4*)((U) + (((zz) << 14) + ((yy) << 7)))) + lane)
    const float4 cA  = __ldg(RP(UA, z,   y )), cB  = __ldg(RP(UB, z,   y ));
    const float4 zmA = __ldg(RP(UA, zm_, y )), zmB = __ldg(RP(UB, zm_, y ));
    const float4 zpA = __ldg(RP(UA, zq,  y )), zpB = __ldg(RP(UB, zq,  y ));
    const float4 ymA = __ldg(RP(UA, z,  ym_)), ymB = __ldg(RP(UB, z,  ym_));
    const float4 ypA = __ldg(RP(UA, z,  yq )), ypB = __ldg(RP(UB, z,  yq ));
    const float4 mmA = __ldg(RP(UA, zm_, ym_)), mmB = __ldg(RP(UB, zm_, ym_));
    const float4 mpA = __ldg(RP(UA, zm_, yq )), mpB = __ldg(RP(UB, zm_, yq ));
    const float4 pmA = __ldg(RP(UA, zq,  ym_)), pmB = __ldg(RP(UB, zq,  ym_));
    const float4 ppA = __ldg(RP(UA, zq,  yq )), ppB = __ldg(RP(UB, zq,  yq ));
    const float4 tA  = __ldg(((const float4*)(yt + vbA + ((z << 14) + (y << 7)))) + lane);
    const float4 tB  = __ldg(((const float4*)(yt + vbA + ((size_t)3 << 21) + ((z << 14) + (y << 7)))) + lane);
    #undef RP

    const Win cen = mkwin(cA,  cB,  lane);
    const Win zmw = mkwin(zmA, zmB, lane);
    const Win zpw = mkwin(zpA, zpB, lane);
    const Win ymw = mkwin(ymA, ymB, lane);
    const Win ypw = mkwin(ypA, ypB, lane);
    const P4  mm  = mkp4(mmA, mmB);
    const P4  mp  = mkp4(mpA, mpB);
    const P4  pm  = mkp4(pmA, pmB);
    const P4  pp  = mkp4(ppA, ppB);
    const P4  tp  = mkp4(tA,  tB);

    u64f2 ain2 = 0ull, aout2 = 0ull;   // packed accumulators (+0.0f|+0.0f)
    float ael = 0.f;

    #pragma unroll
    for (int j = 0; j < 4; j++) {
        const u64f2 uc  = cen.w[j + 1];
        const u64f2 uxm = cen.w[j];
        const u64f2 uxp = cen.w[j + 2];
        const u64f2 uzm = zmw.w[j + 1];
        const u64f2 uzp = zpw.w[j + 1];
        const u64f2 uym = ymw.w[j + 1];
        const u64f2 uyp = ypw.w[j + 1];

        // unscaled first differences (ci = di/2 etc.)
        const u64f2 di = sub2(uzp, uzm);
        const u64f2 dj = sub2(uyp, uym);
        const u64f2 dk = sub2(uxp, uxm);
        const u64f2 di2 = mul2(di, di);
        const u64f2 dj2 = mul2(dj, dj);
        const u64f2 dk2 = mul2(dk, dk);
        const u64f2 S = add2(di2, add2(dj2, dk2));       // = 4*(ci2+cj2+ck2)

        // second derivatives (exact at boundaries)
        const u64f2 cii = fma2_(uc, (u64f2)NEG22, add2(uzp, uzm));
        const u64f2 cjj = fma2_(uc, (u64f2)NEG22, add2(uyp, uym));
        const u64f2 ckk = fma2_(uc, (u64f2)NEG22, add2(uxp, uxm));
        const u64f2 lap = add2(cii, add2(cjj, ckk));

        // unscaled mixed differences (cij = Dij/2 etc.)
        const u64f2 Dij = sub2(sub2(pp.v[j], mp.v[j]), sub2(pm.v[j], mm.v[j]));
        const u64f2 Dik = sub2(sub2(zpw.w[j + 2], zmw.w[j + 2]),
                               sub2(zpw.w[j],     zmw.w[j]));
        const u64f2 Djk = sub2(sub2(ypw.w[j + 2], ymw.w[j + 2]),
                               sub2(ypw.w[j],     ymw.w[j]));

        // curv = lap + 0.25*( S*lap - (di2*cii + dj2*cjj + dk2*ckk) - Dik*Djk*Dij )
        const u64f2 m = mul2(Dik, Djk);
        u64f2 acc = mul2(di2, cii);
        acc = fma2_(dj2, cjj, acc);
        acc = fma2_(dk2, ckk, acc);
        acc = fma2_(m,   Dij, acc);
        const u64f2 t_  = fma2_(acc, (u64f2)NEG12, mul2(S, lap));
        const u64f2 curv = fma2_((u64f2)QTR2, t_, lap);
        const u64f2 curv2 = mul2(curv, curv);
        const u64f2 ee = fma2_((u64f2)QTR2, S, (u64f2)EPS2b); // eps + s
        const u64f2 oo = fma2_((u64f2)QTR2, S, (u64f2)ONE2);  // 1 + s

        // elastica: curv^2 * sqrt(eps+s) / (1+s)
        float c2a, c2b, ea, eb, oa, ob;
        un2(curv2, c2a, c2b); un2(ee, ea, eb); un2(oo, oa, ob);
        ael += __fdividef(c2a * sqrtf(ea), oa);
        ael += __fdividef(c2b * sqrtf(eb), ob);

        // region terms (packed)
        const u64f2 tj  = tp.v[j];
        const u64f2 tm1 = add2(tj, (u64f2)NEG12);
        ain2  = fma2_(uc, mul2(tm1, tm1), ain2);
        const u64f2 omu = fma2_(uc, (u64f2)NEG12, (u64f2)ONE2);
        aout2 = fma2_(omu, mul2(tj, tj), aout2);
    }

    float ain, ainB, aout, aoutB;
    un2(ain2, ain, ainB);   ain  += ainB;
    un2(aout2, aout, aoutB); aout += aoutB;

    // ---- block reduction ----
    #pragma unroll
    for (int o = 16; o > 0; o >>= 1) {
        ain  += __shfl_down_sync(FULL, ain,  o);
        aout += __shfl_down_sync(FULL, aout, o);
        ael  += __shfl_down_sync(FULL, ael,  o);
    }
    __shared__ float si[WPB], so[WPB], se[WPB];
    if (lane == 0) { si[wid] = ain; so[wid] = aout; se[wid] = ael; }
    __syncthreads();

    if (threadIdx.x == 0) {
        float A = si[0] + si[1] + si[2] + si[3];
        float B = so[0] + so[1] + so[2] + so[3];
        float E = se[0] + se[1] + se[2] + se[3];
        atomicAdd(&g_acc[0], (double)A);
        atomicAdd(&g_acc[1], (double)B);
        atomicAdd(&g_acc[2], (double)E);
        __threadfence();
        unsigned t = atomicAdd(&g_ticket, 1u);
        if (t == (unsigned)(GRID - 1)) {           // last block: finalize + reset
            __threadfence();
            double s0 = atomicAdd(&g_acc[0], 0.0);
            double s1 = atomicAdd(&g_acc[1], 0.0);
            double s2 = atomicAdd(&g_acc[2], 0.0);
            double r = fabs(s0) + fabs(s1) + s2 + ALPHA * (double)NTOT;
            out[0] = (float)r;
            g_acc[0] = 0.0; g_acc[1] = 0.0; g_acc[2] = 0.0;
            g_ticket = 0u;
        }
    }
}

extern "C" void kernel_launch(void* const* d_in, const int* in_sizes, int n_in,
                              void* d_out, int out_size) {
    const float* y_pred = (const float*)d_in[0];
    const float* y_true = (const float*)d_in[1];
    ace_main<<<GRID, BLOCK>>>(y_pred, y_true, (float*)d_out);
}